// round 4
// baseline (speedup 1.0000x reference)
#include <cuda_runtime.h>
#include <math.h>

// ---------------------------------------------------------------------------
// Problem constants
// ---------------------------------------------------------------------------
#define BATCH   4096
#define NTOK    64          // window size 8x8
#define CDIM    96
#define NHEADS  3
#define HD      32          // head dim
#define K4      384         // 4*C
#define SCALE   0.17677669529663687f   // 32^-0.5

// ---------------------------------------------------------------------------
// Scratch (device globals: the sanctioned alloc-free workaround)
// ---------------------------------------------------------------------------
__device__ float g_Ys [(size_t)BATCH * NTOK * K4];    // state projections
__device__ float g_Ye [(size_t)BATCH * NTOK * K4];    // input projections
__device__ float g_Mcv[(size_t)BATCH * NTOK * CDIM];
__device__ float g_Msv[(size_t)BATCH * NTOK * CDIM];
__device__ float g_Mch[(size_t)BATCH * NTOK * CDIM];
__device__ float g_Msh[(size_t)BATCH * NTOK * CDIM];

// ---------------------------------------------------------------------------
// Generic GEMM: C[M,Nn] = concat(A1,A2)[M,K] @ W[Nn,K]^T + bias[Nn]
// Tile 64x64, k-chunk 32, 256 threads, 4x4 register blocking.
// M must be a multiple of 64 (262144 here). Nn handled with bounds checks.
// K must be a multiple of 32, Ksplit a multiple of 32.
// ---------------------------------------------------------------------------
#define BM 64
#define BN 64
#define BKC 32
#define APAD 68   // 64 + 4: keeps float4 compute loads aligned & conflict-free

__global__ __launch_bounds__(256)
void gemm_bias(const float* __restrict__ A1, const float* __restrict__ A2,
               int lda1, int lda2, int Ksplit, int K, int Nn,
               const float* __restrict__ W, const float* __restrict__ bias,
               float* __restrict__ Cout)
{
    __shared__ float As[BKC][APAD];
    __shared__ float Bs[BKC][APAD];

    const int t     = threadIdx.x;
    const int mBase = blockIdx.x * BM;
    const int nBase = blockIdx.y * BN;
    const int kk    = t & 31;     // 0..31 : k within chunk
    const int rrow  = t >> 5;     // 0..7
    const int tx    = t & 15;     // m micro-tile
    const int ty    = t >> 4;     // n micro-tile

    float acc[4][4];
    #pragma unroll
    for (int i = 0; i < 4; i++)
        #pragma unroll
        for (int j = 0; j < 4; j++) acc[i][j] = 0.f;

    for (int k0 = 0; k0 < K; k0 += BKC) {
        const float* A;
        int lda, kcol;
        if (k0 < Ksplit) { A = A1; lda = lda1; kcol = k0; }
        else             { A = A2; lda = lda2; kcol = k0 - Ksplit; }

        #pragma unroll
        for (int r = 0; r < 8; r++) {
            int m = rrow + r * 8;
            As[kk][m] = A[(size_t)(mBase + m) * lda + kcol + kk];
        }
        #pragma unroll
        for (int r = 0; r < 8; r++) {
            int n = rrow + r * 8;
            float v = 0.f;
            if (nBase + n < Nn) v = W[(size_t)(nBase + n) * K + k0 + kk];
            Bs[kk][n] = v;
        }
        __syncthreads();

        #pragma unroll
        for (int q = 0; q < BKC; q++) {
            float4 av = *(const float4*)&As[q][tx * 4];
            float4 bv = *(const float4*)&Bs[q][ty * 4];
            float am[4] = {av.x, av.y, av.z, av.w};
            float bn[4] = {bv.x, bv.y, bv.z, bv.w};
            #pragma unroll
            for (int i = 0; i < 4; i++)
                #pragma unroll
                for (int j = 0; j < 4; j++)
                    acc[i][j] = fmaf(am[i], bn[j], acc[i][j]);
        }
        __syncthreads();
    }

    #pragma unroll
    for (int i = 0; i < 4; i++) {
        int row = mBase + tx * 4 + i;
        #pragma unroll
        for (int j = 0; j < 4; j++) {
            int col = nBase + ty * 4 + j;
            if (col < Nn)
                Cout[(size_t)row * Nn + col] = acc[i][j] + bias[col];
        }
    }
}

// ---------------------------------------------------------------------------
// Window attention. Grid (BATCH, NHEADS, 2). 128 threads.
//   z = 0: source = Ys  -> typeA = attn_cv (scale),  typeB = attn_sh (scale^2)
//   z = 1: source = Ye  -> typeA = attn_sv (1.0),    typeB = attn_ch (scale)
// Tiles j4 = 0(k), 1(v), 2(qA), 3(qB) -- identical role for both z.
// 4 warps: warps {0,1} = type A (query-row halves), {2,3} = type B.
// Dynamic smem: 4 q/k/v tiles [64][33] + scores S[2][64][65] = 67072 B.
// ---------------------------------------------------------------------------
#define TPITCH 33
#define TSIZE  (NTOK * TPITCH)     // 2112 floats per tile
#define SPITCH 65
#define ATTN_SMEM ((4 * TSIZE + 2 * NTOK * SPITCH) * sizeof(float))

__global__ __launch_bounds__(128)
void attn_kernel(const float* __restrict__ tcv, const float* __restrict__ tsv,
                 const float* __restrict__ tch, const float* __restrict__ tsh,
                 const int*   __restrict__ rel_idx)
{
    extern __shared__ float smem[];
    float* tiles = smem;                      // 4 * 2112
    float* S     = smem + 4 * TSIZE;          // 2 * 64 * 65

    const int b = blockIdx.x;
    const int h = blockIdx.y;
    const int z = blockIdx.z;

    const float* Y = z ? g_Ye : g_Ys;
    const float* tblA = z ? tsv : tcv;
    const float* tblB = z ? tch : tsh;
    const float  sclA = z ? 1.0f  : SCALE;
    const float  sclB = z ? SCALE : SCALE * SCALE;
    float* outA = z ? g_Msv : g_Mcv;
    float* outB = z ? g_Mch : g_Msh;

    const int t    = threadIdx.x;
    const int lane = t & 31;
    const int warp = t >> 5;

    // ---- load 4 projection tiles [64][32] (cols j4*96 + h*32 + lane) ----
    #pragma unroll
    for (int j4 = 0; j4 < 4; j4++) {
        #pragma unroll
        for (int r = 0; r < 16; r++) {
            int i = warp * 16 + r;
            tiles[j4 * TSIZE + i * TPITCH + lane] =
                Y[(size_t)(b * NTOK + i) * K4 + j4 * CDIM + h * HD + lane];
        }
    }

    // ---- pre-fill scores with relative-position bias ----
    for (int idx = t; idx < NTOK * NTOK; idx += 128) {
        int r = rel_idx[idx];
        int i = idx >> 6, j = idx & 63;
        float ba = tblA[r * NHEADS + h];
        float bb = tblB[r * NHEADS + h];
        S[i * SPITCH + j]                  = ba;
        S[(NTOK + i) * SPITCH + j]         = bb;
    }
    __syncthreads();

    const int type = warp >> 1;     // 0 = A, 1 = B
    const int half = warp & 1;      // query-row half
    const float* q = tiles + (2 + type) * TSIZE;
    const float* k = tiles;                 // j4 = 0
    const float* v = tiles + TSIZE;         // j4 = 1
    const float  scl = type ? sclB : sclA;
    float* St = S + type * NTOK * SPITCH;
    float* outP = type ? outB : outA;

    // ---- Q @ K^T (lane owns columns j0=lane, j1=lane+32; 4-row blocking) ----
    const int j0 = lane, j1 = lane + 32;
    for (int i0 = half * 32; i0 < half * 32 + 32; i0 += 4) {
        float a0[4], a1[4];
        #pragma unroll
        for (int r = 0; r < 4; r++) { a0[r] = 0.f; a1[r] = 0.f; }
        #pragma unroll
        for (int d = 0; d < HD; d++) {
            float k0v = k[j0 * TPITCH + d];
            float k1v = k[j1 * TPITCH + d];
            #pragma unroll
            for (int r = 0; r < 4; r++) {
                float qv = q[(i0 + r) * TPITCH + d];
                a0[r] = fmaf(qv, k0v, a0[r]);
                a1[r] = fmaf(qv, k1v, a1[r]);
            }
        }
        #pragma unroll
        for (int r = 0; r < 4; r++) {
            St[(i0 + r) * SPITCH + j0] = fmaf(scl, a0[r], St[(i0 + r) * SPITCH + j0]);
            St[(i0 + r) * SPITCH + j1] = fmaf(scl, a1[r], St[(i0 + r) * SPITCH + j1]);
        }
    }
    __syncwarp();

    // ---- row softmax (each lane owns one row of its half) ----
    {
        int row = half * 32 + lane;
        float* Sr = St + row * SPITCH;
        float mx = -1e30f;
        #pragma unroll
        for (int j = 0; j < NTOK; j++) mx = fmaxf(mx, Sr[j]);
        float sum = 0.f;
        #pragma unroll
        for (int j = 0; j < NTOK; j++) {
            float e = __expf(Sr[j] - mx);
            Sr[j] = e;
            sum += e;
        }
        float inv = 1.f / sum;
        #pragma unroll
        for (int j = 0; j < NTOK; j++) Sr[j] *= inv;
    }
    __syncwarp();

    // ---- P @ V (lane owns output dim d=lane; 4-row blocking) ----
    for (int i0 = half * 32; i0 < half * 32 + 32; i0 += 4) {
        float acc[4] = {0.f, 0.f, 0.f, 0.f};
        #pragma unroll 8
        for (int j = 0; j < NTOK; j++) {
            float vv = v[j * TPITCH + lane];
            #pragma unroll
            for (int r = 0; r < 4; r++)
                acc[r] = fmaf(St[(i0 + r) * SPITCH + j], vv, acc[r]);
        }
        #pragma unroll
        for (int r = 0; r < 4; r++)
            outP[(size_t)(b * NTOK + i0 + r) * CDIM + h * HD + lane] = acc[r];
    }
}

// ---------------------------------------------------------------------------
// Launch
// ---------------------------------------------------------------------------
extern "C" void kernel_launch(void* const* d_in, const int* in_sizes, int n_in,
                              void* d_out, int out_size)
{
    const float* input_x = (const float*)d_in[0];
    const float* state_x = (const float*)d_in[1];
    const float* Ws      = (const float*)d_in[2];
    const float* bs      = (const float*)d_in[3];
    const float* We      = (const float*)d_in[4];
    const float* be      = (const float*)d_in[5];
    const float* tcv     = (const float*)d_in[6];
    const float* tsv     = (const float*)d_in[7];
    const float* tch     = (const float*)d_in[8];
    const float* tsh     = (const float*)d_in[9];
    const float* Wpv     = (const float*)d_in[10];
    const float* bpv     = (const float*)d_in[11];
    const float* Wph     = (const float*)d_in[12];
    const float* bph     = (const float*)d_in[13];
    const int*   rel_idx = (const int*)d_in[14];

    float* out   = (float*)d_out;
    float* state = out + (size_t)BATCH * NTOK * CDIM;

    float *pYs, *pYe, *pMcv, *pMsv, *pMch, *pMsh;
    cudaGetSymbolAddress((void**)&pYs,  g_Ys);
    cudaGetSymbolAddress((void**)&pYe,  g_Ye);
    cudaGetSymbolAddress((void**)&pMcv, g_Mcv);
    cudaGetSymbolAddress((void**)&pMsv, g_Msv);
    cudaGetSymbolAddress((void**)&pMch, g_Mch);
    cudaGetSymbolAddress((void**)&pMsh, g_Msh);

    cudaFuncSetAttribute(attn_kernel,
                         cudaFuncAttributeMaxDynamicSharedMemorySize,
                         (int)ATTN_SMEM);

    const int M = BATCH * NTOK;          // 262144

    // Stage 1: projections  Y = X @ W^T + b   -> [M, 384]
    {
        dim3 grid(M / BM, K4 / BN);
        gemm_bias<<<grid, 256>>>(state_x, state_x, CDIM, CDIM, CDIM, CDIM, K4,
                                 Ws, bs, pYs);
        gemm_bias<<<grid, 256>>>(input_x, input_x, CDIM, CDIM, CDIM, CDIM, K4,
                                 We, be, pYe);
    }

    // Stage 2: 4 window attentions per (b, h)
    {
        dim3 grid(BATCH, NHEADS, 2);
        attn_kernel<<<grid, 128, ATTN_SMEM>>>(tcv, tsv, tch, tsh, rel_idx);
    }

    // Stage 3: output projections on concatenated merges
    {
        dim3 grid(M / BM, (CDIM + BN - 1) / BN);   // (4096, 2)
        gemm_bias<<<grid, 256>>>(pMcv, pMsv, CDIM, CDIM, CDIM, 2 * CDIM, CDIM,
                                 Wpv, bpv, out);
        gemm_bias<<<grid, 256>>>(pMch, pMsh, CDIM, CDIM, CDIM, 2 * CDIM, CDIM,
                                 Wph, bph, state);
    }
}

// round 5
// speedup vs baseline: 1.1966x; 1.1966x over previous
#include <cuda_runtime.h>
#include <math.h>

// ---------------------------------------------------------------------------
// Problem constants
// ---------------------------------------------------------------------------
#define BATCH   4096
#define NTOK    64          // window size 8x8
#define CDIM    96
#define NHEADS  3
#define HD      32          // head dim
#define K4      384         // 4*C
#define SCALE   0.17677669529663687f   // 32^-0.5

// ---------------------------------------------------------------------------
// Scratch (device globals: the sanctioned alloc-free workaround)
// ---------------------------------------------------------------------------
__device__ float g_Ys [(size_t)BATCH * NTOK * K4];    // state projections
__device__ float g_Ye [(size_t)BATCH * NTOK * K4];    // input projections
__device__ float g_Mcv[(size_t)BATCH * NTOK * CDIM];
__device__ float g_Msv[(size_t)BATCH * NTOK * CDIM];
__device__ float g_Mch[(size_t)BATCH * NTOK * CDIM];
__device__ float g_Msh[(size_t)BATCH * NTOK * CDIM];

// ---------------------------------------------------------------------------
// GEMM: C[M,Nn] = concat(A1,A2)[M,K] @ W[Nn,K]^T + bias[Nn]
// Tile 128x128, k-chunk 16, 256 threads, 8x8 register blocking (split rows:
// {tx*4..tx*4+3} U {64+tx*4..}, same for columns) -> conflict-free LDS.128.
// M multiple of 128. Nn, with Nn % 4 == 0, handled by whole-float4 guards.
// K multiple of 16, Ksplit multiple of 16.
// ---------------------------------------------------------------------------
#define BM 128
#define BN 128
#define BKC 16
#define APAD 132   // 128 + 4

__global__ __launch_bounds__(256)
void gemm_bias(const float* __restrict__ A1, const float* __restrict__ A2,
               int lda1, int lda2, int Ksplit, int K, int Nn,
               const float* __restrict__ W, const float* __restrict__ bias,
               float* __restrict__ Cout)
{
    __shared__ float As[BKC][APAD];
    __shared__ float Bs[BKC][APAD];

    const int t     = threadIdx.x;
    const int mBase = blockIdx.x * BM;
    const int nBase = blockIdx.y * BN;
    const int kk    = t & 15;     // 0..15 : k within chunk
    const int rrow  = t >> 4;     // 0..15
    const int tx    = t & 15;     // m micro-tile
    const int ty    = t >> 4;     // n micro-tile

    float acc[8][8];
    #pragma unroll
    for (int i = 0; i < 8; i++)
        #pragma unroll
        for (int j = 0; j < 8; j++) acc[i][j] = 0.f;

    for (int k0 = 0; k0 < K; k0 += BKC) {
        const float* A;
        int lda, kcol;
        if (k0 < Ksplit) { A = A1; lda = lda1; kcol = k0; }
        else             { A = A2; lda = lda2; kcol = k0 - Ksplit; }

        #pragma unroll
        for (int r = 0; r < 8; r++) {
            int m = rrow + r * 16;
            As[kk][m] = A[(size_t)(mBase + m) * lda + kcol + kk];
        }
        #pragma unroll
        for (int r = 0; r < 8; r++) {
            int n = rrow + r * 16;
            float v = 0.f;
            if (nBase + n < Nn) v = W[(size_t)(nBase + n) * K + k0 + kk];
            Bs[kk][n] = v;
        }
        __syncthreads();

        #pragma unroll
        for (int q = 0; q < BKC; q++) {
            float4 a0 = *(const float4*)&As[q][tx * 4];
            float4 a1 = *(const float4*)&As[q][64 + tx * 4];
            float4 b0 = *(const float4*)&Bs[q][ty * 4];
            float4 b1 = *(const float4*)&Bs[q][64 + ty * 4];
            float am[8] = {a0.x, a0.y, a0.z, a0.w, a1.x, a1.y, a1.z, a1.w};
            float bn[8] = {b0.x, b0.y, b0.z, b0.w, b1.x, b1.y, b1.z, b1.w};
            #pragma unroll
            for (int i = 0; i < 8; i++)
                #pragma unroll
                for (int j = 0; j < 8; j++)
                    acc[i][j] = fmaf(am[i], bn[j], acc[i][j]);
        }
        __syncthreads();
    }

    // Epilogue: float4 stores; Nn % 4 == 0 and groups are 4-aligned, so each
    // 4-col group is entirely in or out of range.
    #pragma unroll
    for (int ih = 0; ih < 2; ih++) {
        #pragma unroll
        for (int i = 0; i < 4; i++) {
            int row = mBase + ih * 64 + tx * 4 + i;
            #pragma unroll
            for (int jh = 0; jh < 2; jh++) {
                int col = nBase + jh * 64 + ty * 4;
                if (col < Nn) {
                    float4 bv = *(const float4*)&bias[col];
                    float4 r;
                    r.x = acc[ih * 4 + i][jh * 4 + 0] + bv.x;
                    r.y = acc[ih * 4 + i][jh * 4 + 1] + bv.y;
                    r.z = acc[ih * 4 + i][jh * 4 + 2] + bv.z;
                    r.w = acc[ih * 4 + i][jh * 4 + 3] + bv.w;
                    *(float4*)&Cout[(size_t)row * Nn + col] = r;
                }
            }
        }
    }
}

// ---------------------------------------------------------------------------
// Window attention. Grid (BATCH, NHEADS, 2). 128 threads, 4 warps.
//   z = 0: source = Ys  -> typeA = attn_cv (scale),  typeB = attn_sh (scale^2)
//   z = 1: source = Ye  -> typeA = attn_sv (1.0),    typeB = attn_ch (scale)
// warps {0,1} = type A (row halves), {2,3} = type B. Lane owns ONE query row:
//   - q row (32 f) in registers (conflict-free LDS.128, pitch 36)
//   - K/V read as broadcast float4 (all lanes same address)
//   - scores live in the bias smem buffer (pitch 65, conflict-free)
//   - softmax normalization folded into the 32 outputs
// ---------------------------------------------------------------------------
#define TP 36                                  // tile pitch (floats)
#define TSZ (NTOK * TP)                        // 2304 floats per tile
#define SP 65                                  // score/bias pitch
#define ATTN_SMEM ((4 * TSZ + 2 * NTOK * SP) * sizeof(float))   // 70144 B

__global__ __launch_bounds__(128)
void attn_kernel(const float* __restrict__ tcv, const float* __restrict__ tsv,
                 const float* __restrict__ tch, const float* __restrict__ tsh,
                 const int*   __restrict__ rel_idx)
{
    extern __shared__ float sm[];
    float* tiles = sm;                 // [4][64][TP]
    float* biasS = sm + 4 * TSZ;       // [2][64][SP] : bias, then scores

    const int b = blockIdx.x;
    const int h = blockIdx.y;
    const int z = blockIdx.z;

    const float* Y    = z ? g_Ye : g_Ys;
    const float* tblA = z ? tsv : tcv;
    const float* tblB = z ? tch : tsh;
    const float  sclA = z ? 1.0f  : SCALE;
    const float  sclB = z ? SCALE : SCALE * SCALE;
    float* outAp = z ? g_Msv : g_Mcv;
    float* outBp = z ? g_Mch : g_Msh;

    const int t    = threadIdx.x;
    const int lane = t & 31;
    const int warp = t >> 5;

    // ---- load 4 projection tiles [64][32] (cols j4*96 + h*32 + lane) ----
    #pragma unroll
    for (int j4 = 0; j4 < 4; j4++) {
        #pragma unroll
        for (int r = 0; r < 16; r++) {
            int i = warp * 16 + r;
            tiles[j4 * TSZ + i * TP + lane] =
                Y[(size_t)(b * NTOK + i) * K4 + j4 * CDIM + h * HD + lane];
        }
    }

    // ---- gather relative-position bias into score buffer ----
    for (int idx = t; idx < NTOK * NTOK; idx += 128) {
        int r = rel_idx[idx];
        int i = idx >> 6, j = idx & 63;
        biasS[i * SP + j]                  = tblA[r * NHEADS + h];
        biasS[NTOK * SP + i * SP + j]      = tblB[r * NHEADS + h];
    }
    __syncthreads();

    const int   type = warp >> 1;     // 0 = A, 1 = B
    const int   half = warp & 1;      // query-row half
    const int   row  = half * 32 + lane;
    const float scl  = type ? sclB : sclA;
    const float* Kt  = tiles;                 // j4 = 0 (keys)
    const float* Vt  = tiles + TSZ;           // j4 = 1 (values)
    const float* qp  = tiles + (2 + type) * TSZ + row * TP;
    float* St        = biasS + type * NTOK * SP + row * SP;   // my score row
    float* outP      = type ? outBp : outAp;

    // ---- q row into registers (8 conflict-free LDS.128) ----
    float qr[32];
    #pragma unroll
    for (int c = 0; c < 8; c++) {
        float4 v4 = *(const float4*)(qp + 4 * c);
        qr[4 * c + 0] = v4.x; qr[4 * c + 1] = v4.y;
        qr[4 * c + 2] = v4.z; qr[4 * c + 3] = v4.w;
    }

    // ---- scores: S[row][j] = scl * <q_row, k_j> + bias ----
    #pragma unroll 4
    for (int j = 0; j < NTOK; j++) {
        const float* kj = Kt + j * TP;
        float s0 = 0.f, s1 = 0.f, s2 = 0.f, s3 = 0.f;
        #pragma unroll
        for (int c = 0; c < 8; c++) {
            float4 kv = *(const float4*)(kj + 4 * c);   // broadcast
            s0 = fmaf(qr[4 * c + 0], kv.x, s0);
            s1 = fmaf(qr[4 * c + 1], kv.y, s1);
            s2 = fmaf(qr[4 * c + 2], kv.z, s2);
            s3 = fmaf(qr[4 * c + 3], kv.w, s3);
        }
        St[j] = fmaf(scl, (s0 + s1) + (s2 + s3), St[j]);
    }

    // ---- softmax over my row (normalization deferred to outputs) ----
    float mx = -1e30f;
    #pragma unroll
    for (int j = 0; j < NTOK; j++) mx = fmaxf(mx, St[j]);
    float sum = 0.f;
    #pragma unroll
    for (int j = 0; j < NTOK; j++) {
        float e = __expf(St[j] - mx);
        St[j] = e;
        sum += e;
    }
    const float inv = 1.f / sum;

    // ---- out[d] = inv * sum_j p_j * V[j][d], d = 0..31 in registers ----
    float ou[32];
    #pragma unroll
    for (int c = 0; c < 32; c++) ou[c] = 0.f;
    #pragma unroll 4
    for (int j = 0; j < NTOK; j++) {
        const float p = St[j];
        const float* vj = Vt + j * TP;
        #pragma unroll
        for (int c = 0; c < 8; c++) {
            float4 vv = *(const float4*)(vj + 4 * c);   // broadcast
            ou[4 * c + 0] = fmaf(p, vv.x, ou[4 * c + 0]);
            ou[4 * c + 1] = fmaf(p, vv.y, ou[4 * c + 1]);
            ou[4 * c + 2] = fmaf(p, vv.z, ou[4 * c + 2]);
            ou[4 * c + 3] = fmaf(p, vv.w, ou[4 * c + 3]);
        }
    }
    float* op = outP + (size_t)(b * NTOK + row) * CDIM + h * HD;
    #pragma unroll
    for (int c = 0; c < 8; c++) {
        float4 r;
        r.x = ou[4 * c + 0] * inv;
        r.y = ou[4 * c + 1] * inv;
        r.z = ou[4 * c + 2] * inv;
        r.w = ou[4 * c + 3] * inv;
        *(float4*)(op + 4 * c) = r;
    }
}

// ---------------------------------------------------------------------------
// Launch
// ---------------------------------------------------------------------------
extern "C" void kernel_launch(void* const* d_in, const int* in_sizes, int n_in,
                              void* d_out, int out_size)
{
    const float* input_x = (const float*)d_in[0];
    const float* state_x = (const float*)d_in[1];
    const float* Ws      = (const float*)d_in[2];
    const float* bs      = (const float*)d_in[3];
    const float* We      = (const float*)d_in[4];
    const float* be      = (const float*)d_in[5];
    const float* tcv     = (const float*)d_in[6];
    const float* tsv     = (const float*)d_in[7];
    const float* tch     = (const float*)d_in[8];
    const float* tsh     = (const float*)d_in[9];
    const float* Wpv     = (const float*)d_in[10];
    const float* bpv     = (const float*)d_in[11];
    const float* Wph     = (const float*)d_in[12];
    const float* bph     = (const float*)d_in[13];
    const int*   rel_idx = (const int*)d_in[14];

    float* out   = (float*)d_out;
    float* state = out + (size_t)BATCH * NTOK * CDIM;

    float *pYs, *pYe, *pMcv, *pMsv, *pMch, *pMsh;
    cudaGetSymbolAddress((void**)&pYs,  g_Ys);
    cudaGetSymbolAddress((void**)&pYe,  g_Ye);
    cudaGetSymbolAddress((void**)&pMcv, g_Mcv);
    cudaGetSymbolAddress((void**)&pMsv, g_Msv);
    cudaGetSymbolAddress((void**)&pMch, g_Mch);
    cudaGetSymbolAddress((void**)&pMsh, g_Msh);

    cudaFuncSetAttribute(attn_kernel,
                         cudaFuncAttributeMaxDynamicSharedMemorySize,
                         (int)ATTN_SMEM);

    const int M = BATCH * NTOK;          // 262144

    // Stage 1: projections  Y = X @ W^T + b   -> [M, 384]
    {
        dim3 grid(M / BM, K4 / BN);      // (2048, 3)
        gemm_bias<<<grid, 256>>>(state_x, state_x, CDIM, CDIM, CDIM, CDIM, K4,
                                 Ws, bs, pYs);
        gemm_bias<<<grid, 256>>>(input_x, input_x, CDIM, CDIM, CDIM, CDIM, K4,
                                 We, be, pYe);
    }

    // Stage 2: 4 window attentions per (b, h)
    {
        dim3 grid(BATCH, NHEADS, 2);
        attn_kernel<<<grid, 128, ATTN_SMEM>>>(tcv, tsv, tch, tsh, rel_idx);
    }

    // Stage 3: output projections on concatenated merges
    {
        dim3 grid(M / BM, (CDIM + BN - 1) / BN);   // (2048, 1)
        gemm_bias<<<grid, 256>>>(pMcv, pMsv, CDIM, CDIM, CDIM, 2 * CDIM, CDIM,
                                 Wpv, bpv, out);
        gemm_bias<<<grid, 256>>>(pMch, pMsh, CDIM, CDIM, CDIM, 2 * CDIM, CDIM,
                                 Wph, bph, state);
    }
}

// round 6
// speedup vs baseline: 1.3462x; 1.1251x over previous
#include <cuda_runtime.h>
#include <math.h>

// ---------------------------------------------------------------------------
// Problem constants
// ---------------------------------------------------------------------------
#define BATCH   4096
#define NTOK    64          // window size 8x8
#define CDIM    96
#define NHEADS  3
#define HD      32          // head dim
#define K4      384         // 4*C
#define SCALE   0.17677669529663687f   // 32^-0.5

// ---------------------------------------------------------------------------
// Scratch (device globals: the sanctioned alloc-free workaround)
// ---------------------------------------------------------------------------
__device__ float g_Ys [(size_t)BATCH * NTOK * K4];    // state projections
__device__ float g_Ye [(size_t)BATCH * NTOK * K4];    // input projections
__device__ float g_Mcv[(size_t)BATCH * NTOK * CDIM];
__device__ float g_Msv[(size_t)BATCH * NTOK * CDIM];
__device__ float g_Mch[(size_t)BATCH * NTOK * CDIM];
__device__ float g_Msh[(size_t)BATCH * NTOK * CDIM];

// ---------------------------------------------------------------------------
// Fast exp on the FMA pipe (no MUFU). Valid for x in [-87, 0]; rel err ~2e-6.
// exp(x) = 2^(x*log2e); round-to-nearest via magic constant, degree-5 poly
// for 2^f on f in [-0.5, 0.5], then splice integer part into the exponent.
// ---------------------------------------------------------------------------
__device__ __forceinline__ float fast_exp(float x)
{
    const float L2E   = 1.4426950408889634f;
    const float MAGIC = 12582912.0f;          // 1.5 * 2^23
    float y = x * L2E;
    float t = y + MAGIC;
    float f = y - (t - MAGIC);                // f in [-0.5, 0.5]
    int   i = __float_as_int(t) - 0x4B400000; // round(y)
    float p = 1.33335581e-3f;
    p = fmaf(p, f, 9.61804886e-3f);
    p = fmaf(p, f, 5.55041087e-2f);
    p = fmaf(p, f, 2.40226507e-1f);
    p = fmaf(p, f, 6.93147182e-1f);
    p = fmaf(p, f, 1.0f);
    return __int_as_float(__float_as_int(p) + (i << 23));
}

// ---------------------------------------------------------------------------
// GEMM: C[M,Nn] = concat(A1,A2)[M,K] @ W[Nn,K]^T + bias[Nn]
// Tile 128x128, k-chunk 16, 256 threads, 8x8 register blocking (split rows:
// {tx*4..tx*4+3} U {64+tx*4..}, same for columns) -> conflict-free LDS.128.
// __launch_bounds__(256, 2): cap 128 regs so 2 CTAs/SM (16 warps) fit.
// ---------------------------------------------------------------------------
#define BM 128
#define BN 128
#define BKC 16
#define APAD 132   // 128 + 4

__global__ __launch_bounds__(256, 2)
void gemm_bias(const float* __restrict__ A1, const float* __restrict__ A2,
               int lda1, int lda2, int Ksplit, int K, int Nn,
               const float* __restrict__ W, const float* __restrict__ bias,
               float* __restrict__ Cout)
{
    __shared__ float As[BKC][APAD];
    __shared__ float Bs[BKC][APAD];

    const int t     = threadIdx.x;
    const int mBase = blockIdx.x * BM;
    const int nBase = blockIdx.y * BN;
    const int kk    = t & 15;     // 0..15 : k within chunk
    const int rrow  = t >> 4;     // 0..15
    const int tx    = t & 15;     // m micro-tile
    const int ty    = t >> 4;     // n micro-tile

    float acc[8][8];
    #pragma unroll
    for (int i = 0; i < 8; i++)
        #pragma unroll
        for (int j = 0; j < 8; j++) acc[i][j] = 0.f;

    for (int k0 = 0; k0 < K; k0 += BKC) {
        const float* A;
        int lda, kcol;
        if (k0 < Ksplit) { A = A1; lda = lda1; kcol = k0; }
        else             { A = A2; lda = lda2; kcol = k0 - Ksplit; }

        #pragma unroll
        for (int r = 0; r < 8; r++) {
            int m = rrow + r * 16;
            As[kk][m] = A[(size_t)(mBase + m) * lda + kcol + kk];
        }
        #pragma unroll
        for (int r = 0; r < 8; r++) {
            int n = rrow + r * 16;
            float v = 0.f;
            if (nBase + n < Nn) v = W[(size_t)(nBase + n) * K + k0 + kk];
            Bs[kk][n] = v;
        }
        __syncthreads();

        #pragma unroll
        for (int q = 0; q < BKC; q++) {
            float4 a0 = *(const float4*)&As[q][tx * 4];
            float4 a1 = *(const float4*)&As[q][64 + tx * 4];
            float4 b0 = *(const float4*)&Bs[q][ty * 4];
            float4 b1 = *(const float4*)&Bs[q][64 + ty * 4];
            float am[8] = {a0.x, a0.y, a0.z, a0.w, a1.x, a1.y, a1.z, a1.w};
            float bn[8] = {b0.x, b0.y, b0.z, b0.w, b1.x, b1.y, b1.z, b1.w};
            #pragma unroll
            for (int i = 0; i < 8; i++)
                #pragma unroll
                for (int j = 0; j < 8; j++)
                    acc[i][j] = fmaf(am[i], bn[j], acc[i][j]);
        }
        __syncthreads();
    }

    // Epilogue: float4 stores; Nn % 4 == 0 and groups are 4-aligned, so each
    // 4-col group is entirely in or out of range.
    #pragma unroll
    for (int ih = 0; ih < 2; ih++) {
        #pragma unroll
        for (int i = 0; i < 4; i++) {
            int row = mBase + ih * 64 + tx * 4 + i;
            #pragma unroll
            for (int jh = 0; jh < 2; jh++) {
                int col = nBase + jh * 64 + ty * 4;
                if (col < Nn) {
                    float4 bv = *(const float4*)&bias[col];
                    float4 r;
                    r.x = acc[ih * 4 + i][jh * 4 + 0] + bv.x;
                    r.y = acc[ih * 4 + i][jh * 4 + 1] + bv.y;
                    r.z = acc[ih * 4 + i][jh * 4 + 2] + bv.z;
                    r.w = acc[ih * 4 + i][jh * 4 + 3] + bv.w;
                    *(float4*)&Cout[(size_t)row * Nn + col] = r;
                }
            }
        }
    }
}

// ---------------------------------------------------------------------------
// Window attention. Grid (BATCH, NHEADS, 2). 128 threads, 4 warps.
//   z = 0: source = Ys  -> typeA = attn_cv (scale),  typeB = attn_sh (scale^2)
//   z = 1: source = Ye  -> typeA = attn_sv (1.0),    typeB = attn_ch (scale)
// warps {0,1} = type A (row halves), {2,3} = type B. Lane owns ONE query row:
//   - q row (32 f) in registers (conflict-free LDS.128, pitch 36)
//   - K/V read as broadcast float4 (all lanes same address)
//   - scores live in the bias smem buffer (pitch 65, conflict-free)
//   - softmax uses FMA-pipe fast_exp (no MUFU); normalization deferred
// ---------------------------------------------------------------------------
#define TP 36                                  // tile pitch (floats)
#define TSZ (NTOK * TP)                        // 2304 floats per tile
#define SP 65                                  // score/bias pitch
#define ATTN_SMEM ((4 * TSZ + 2 * NTOK * SP) * sizeof(float))   // 70144 B

__global__ __launch_bounds__(128)
void attn_kernel(const float* __restrict__ tcv, const float* __restrict__ tsv,
                 const float* __restrict__ tch, const float* __restrict__ tsh,
                 const int*   __restrict__ rel_idx)
{
    extern __shared__ float sm[];
    float* tiles = sm;                 // [4][64][TP]
    float* biasS = sm + 4 * TSZ;       // [2][64][SP] : bias, then scores

    const int b = blockIdx.x;
    const int h = blockIdx.y;
    const int z = blockIdx.z;

    const float* Y    = z ? g_Ye : g_Ys;
    const float* tblA = z ? tsv : tcv;
    const float* tblB = z ? tch : tsh;
    const float  sclA = z ? 1.0f  : SCALE;
    const float  sclB = z ? SCALE : SCALE * SCALE;
    float* outAp = z ? g_Msv : g_Mcv;
    float* outBp = z ? g_Mch : g_Msh;

    const int t    = threadIdx.x;
    const int lane = t & 31;
    const int warp = t >> 5;

    // ---- load 4 projection tiles [64][32] (cols j4*96 + h*32 + lane) ----
    #pragma unroll
    for (int j4 = 0; j4 < 4; j4++) {
        #pragma unroll
        for (int r = 0; r < 16; r++) {
            int i = warp * 16 + r;
            tiles[j4 * TSZ + i * TP + lane] =
                Y[(size_t)(b * NTOK + i) * K4 + j4 * CDIM + h * HD + lane];
        }
    }

    // ---- gather relative-position bias into score buffer ----
    for (int idx = t; idx < NTOK * NTOK; idx += 128) {
        int r = rel_idx[idx];
        int i = idx >> 6, j = idx & 63;
        biasS[i * SP + j]                  = tblA[r * NHEADS + h];
        biasS[NTOK * SP + i * SP + j]      = tblB[r * NHEADS + h];
    }
    __syncthreads();

    const int   type = warp >> 1;     // 0 = A, 1 = B
    const int   half = warp & 1;      // query-row half
    const int   row  = half * 32 + lane;
    const float scl  = type ? sclB : sclA;
    const float* Kt  = tiles;                 // j4 = 0 (keys)
    const float* Vt  = tiles + TSZ;           // j4 = 1 (values)
    const float* qp  = tiles + (2 + type) * TSZ + row * TP;
    float* St        = biasS + type * NTOK * SP + row * SP;   // my score row
    float* outP      = type ? outBp : outAp;

    // ---- q row into registers (8 conflict-free LDS.128) ----
    float qr[32];
    #pragma unroll
    for (int c = 0; c < 8; c++) {
        float4 v4 = *(const float4*)(qp + 4 * c);
        qr[4 * c + 0] = v4.x; qr[4 * c + 1] = v4.y;
        qr[4 * c + 2] = v4.z; qr[4 * c + 3] = v4.w;
    }

    // ---- scores: S[row][j] = scl * <q_row, k_j> + bias ----
    #pragma unroll 4
    for (int j = 0; j < NTOK; j++) {
        const float* kj = Kt + j * TP;
        float s0 = 0.f, s1 = 0.f, s2 = 0.f, s3 = 0.f;
        #pragma unroll
        for (int c = 0; c < 8; c++) {
            float4 kv = *(const float4*)(kj + 4 * c);   // broadcast
            s0 = fmaf(qr[4 * c + 0], kv.x, s0);
            s1 = fmaf(qr[4 * c + 1], kv.y, s1);
            s2 = fmaf(qr[4 * c + 2], kv.z, s2);
            s3 = fmaf(qr[4 * c + 3], kv.w, s3);
        }
        St[j] = fmaf(scl, (s0 + s1) + (s2 + s3), St[j]);
    }

    // ---- softmax over my row (FMA-pipe exp; normalization deferred) ----
    float mx = -1e30f;
    #pragma unroll
    for (int j = 0; j < NTOK; j++) mx = fmaxf(mx, St[j]);
    float sum = 0.f;
    #pragma unroll
    for (int j = 0; j < NTOK; j++) {
        float e = fast_exp(St[j] - mx);
        St[j] = e;
        sum += e;
    }
    const float inv = 1.f / sum;

    // ---- out[d] = inv * sum_j p_j * V[j][d], d = 0..31 in registers ----
    float ou[32];
    #pragma unroll
    for (int c = 0; c < 32; c++) ou[c] = 0.f;
    #pragma unroll 4
    for (int j = 0; j < NTOK; j++) {
        const float p = St[j];
        const float* vj = Vt + j * TP;
        #pragma unroll
        for (int c = 0; c < 8; c++) {
            float4 vv = *(const float4*)(vj + 4 * c);   // broadcast
            ou[4 * c + 0] = fmaf(p, vv.x, ou[4 * c + 0]);
            ou[4 * c + 1] = fmaf(p, vv.y, ou[4 * c + 1]);
            ou[4 * c + 2] = fmaf(p, vv.z, ou[4 * c + 2]);
            ou[4 * c + 3] = fmaf(p, vv.w, ou[4 * c + 3]);
        }
    }
    float* op = outP + (size_t)(b * NTOK + row) * CDIM + h * HD;
    #pragma unroll
    for (int c = 0; c < 8; c++) {
        float4 r;
        r.x = ou[4 * c + 0] * inv;
        r.y = ou[4 * c + 1] * inv;
        r.z = ou[4 * c + 2] * inv;
        r.w = ou[4 * c + 3] * inv;
        *(float4*)(op + 4 * c) = r;
    }
}

// ---------------------------------------------------------------------------
// Launch
// ---------------------------------------------------------------------------
extern "C" void kernel_launch(void* const* d_in, const int* in_sizes, int n_in,
                              void* d_out, int out_size)
{
    const float* input_x = (const float*)d_in[0];
    const float* state_x = (const float*)d_in[1];
    const float* Ws      = (const float*)d_in[2];
    const float* bs      = (const float*)d_in[3];
    const float* We      = (const float*)d_in[4];
    const float* be      = (const float*)d_in[5];
    const float* tcv     = (const float*)d_in[6];
    const float* tsv     = (const float*)d_in[7];
    const float* tch     = (const float*)d_in[8];
    const float* tsh     = (const float*)d_in[9];
    const float* Wpv     = (const float*)d_in[10];
    const float* bpv     = (const float*)d_in[11];
    const float* Wph     = (const float*)d_in[12];
    const float* bph     = (const float*)d_in[13];
    const int*   rel_idx = (const int*)d_in[14];

    float* out   = (float*)d_out;
    float* state = out + (size_t)BATCH * NTOK * CDIM;

    float *pYs, *pYe, *pMcv, *pMsv, *pMch, *pMsh;
    cudaGetSymbolAddress((void**)&pYs,  g_Ys);
    cudaGetSymbolAddress((void**)&pYe,  g_Ye);
    cudaGetSymbolAddress((void**)&pMcv, g_Mcv);
    cudaGetSymbolAddress((void**)&pMsv, g_Msv);
    cudaGetSymbolAddress((void**)&pMch, g_Mch);
    cudaGetSymbolAddress((void**)&pMsh, g_Msh);

    cudaFuncSetAttribute(attn_kernel,
                         cudaFuncAttributeMaxDynamicSharedMemorySize,
                         (int)ATTN_SMEM);

    const int M = BATCH * NTOK;          // 262144

    // Stage 1: projections  Y = X @ W^T + b   -> [M, 384]
    {
        dim3 grid(M / BM, K4 / BN);      // (2048, 3)
        gemm_bias<<<grid, 256>>>(state_x, state_x, CDIM, CDIM, CDIM, CDIM, K4,
                                 Ws, bs, pYs);
        gemm_bias<<<grid, 256>>>(input_x, input_x, CDIM, CDIM, CDIM, CDIM, K4,
                                 We, be, pYe);
    }

    // Stage 2: 4 window attentions per (b, h)
    {
        dim3 grid(BATCH, NHEADS, 2);
        attn_kernel<<<grid, 128, ATTN_SMEM>>>(tcv, tsv, tch, tsh, rel_idx);
    }

    // Stage 3: output projections on concatenated merges
    {
        dim3 grid(M / BM, (CDIM + BN - 1) / BN);   // (2048, 1)
        gemm_bias<<<grid, 256>>>(pMcv, pMsv, CDIM, CDIM, CDIM, 2 * CDIM, CDIM,
                                 Wpv, bpv, out);
        gemm_bias<<<grid, 256>>>(pMch, pMsh, CDIM, CDIM, CDIM, 2 * CDIM, CDIM,
                                 Wph, bph, state);
    }
}

// round 7
// speedup vs baseline: 1.5076x; 1.1199x over previous
#include <cuda_runtime.h>
#include <math.h>

// ---------------------------------------------------------------------------
// Problem constants
// ---------------------------------------------------------------------------
#define BATCH   4096
#define NTOK    64          // window size 8x8
#define CDIM    96
#define NHEADS  3
#define HD      32          // head dim
#define K4      384         // 4*C
#define SCALE   0.17677669529663687f   // 32^-0.5

// ---------------------------------------------------------------------------
// Scratch (device globals: the sanctioned alloc-free workaround)
// ---------------------------------------------------------------------------
__device__ float g_Ys [(size_t)BATCH * NTOK * K4];    // state projections
__device__ float g_Ye [(size_t)BATCH * NTOK * K4];    // input projections
__device__ float g_Mcv[(size_t)BATCH * NTOK * CDIM];
__device__ float g_Msv[(size_t)BATCH * NTOK * CDIM];
__device__ float g_Mch[(size_t)BATCH * NTOK * CDIM];
__device__ float g_Msh[(size_t)BATCH * NTOK * CDIM];

// ---------------------------------------------------------------------------
// Packed f32x2 helpers (sm_103a FFMA2 path; full fp32 precision)
// ---------------------------------------------------------------------------
typedef unsigned long long u64;

__device__ __forceinline__ u64 pack2(float lo, float hi)
{
    u64 r;
    asm("mov.b64 %0, {%1, %2};" : "=l"(r)
        : "r"(__float_as_uint(lo)), "r"(__float_as_uint(hi)));
    return r;
}
__device__ __forceinline__ void unpack2(float& lo, float& hi, u64 v)
{
    unsigned a, b;
    asm("mov.b64 {%0, %1}, %2;" : "=r"(a), "=r"(b) : "l"(v));
    lo = __uint_as_float(a);
    hi = __uint_as_float(b);
}
__device__ __forceinline__ void fma2(u64& d, u64 a, u64 b)
{
    asm("fma.rn.f32x2 %0, %1, %2, %0;" : "+l"(d) : "l"(a), "l"(b));
}

// ---------------------------------------------------------------------------
// Fast exp on the FMA pipe (no MUFU). Valid for x in [-87, 0]; rel err ~2e-6.
// ---------------------------------------------------------------------------
__device__ __forceinline__ float fast_exp(float x)
{
    const float L2E   = 1.4426950408889634f;
    const float MAGIC = 12582912.0f;          // 1.5 * 2^23
    float y = x * L2E;
    float t = y + MAGIC;
    float f = y - (t - MAGIC);                // f in [-0.5, 0.5]
    int   i = __float_as_int(t) - 0x4B400000; // round(y)
    float p = 1.33335581e-3f;
    p = fmaf(p, f, 9.61804886e-3f);
    p = fmaf(p, f, 5.55041087e-2f);
    p = fmaf(p, f, 2.40226507e-1f);
    p = fmaf(p, f, 6.93147182e-1f);
    p = fmaf(p, f, 1.0f);
    return __int_as_float(__float_as_int(p) + (i << 23));
}

// ---------------------------------------------------------------------------
// GEMM: C[M,Nn] = concat(A1,A2)[M,K] @ W[Nn,K]^T + bias[Nn]
// Tile 128x128, k-chunk 16, 256 threads, 8x8 micro-tile, FFMA2 inner loop.
// acc held as 8 x 4 packed f32x2 pairs (pair = adjacent output columns).
// ---------------------------------------------------------------------------
#define BM 128
#define BN 128
#define BKC 16
#define APAD 132   // 128 + 4

__global__ __launch_bounds__(256, 2)
void gemm_bias(const float* __restrict__ A1, const float* __restrict__ A2,
               int lda1, int lda2, int Ksplit, int K, int Nn,
               const float* __restrict__ W, const float* __restrict__ bias,
               float* __restrict__ Cout)
{
    __shared__ float As[BKC][APAD];
    __shared__ float Bs[BKC][APAD];

    const int t     = threadIdx.x;
    const int mBase = blockIdx.x * BM;
    const int nBase = blockIdx.y * BN;
    const int kk    = t & 15;     // 0..15 : k within chunk
    const int rrow  = t >> 4;     // 0..15
    const int tx    = t & 15;     // m micro-tile
    const int ty    = t >> 4;     // n micro-tile

    u64 acc[8][4];                // [m-row][col-pair]
    #pragma unroll
    for (int i = 0; i < 8; i++)
        #pragma unroll
        for (int j = 0; j < 4; j++) acc[i][j] = 0ull;   // bits 0 == {0.f, 0.f}

    for (int k0 = 0; k0 < K; k0 += BKC) {
        const float* A;
        int lda, kcol;
        if (k0 < Ksplit) { A = A1; lda = lda1; kcol = k0; }
        else             { A = A2; lda = lda2; kcol = k0 - Ksplit; }

        #pragma unroll
        for (int r = 0; r < 8; r++) {
            int m = rrow + r * 16;
            As[kk][m] = A[(size_t)(mBase + m) * lda + kcol + kk];
        }
        #pragma unroll
        for (int r = 0; r < 8; r++) {
            int n = rrow + r * 16;
            float v = 0.f;
            if (nBase + n < Nn) v = W[(size_t)(nBase + n) * K + k0 + kk];
            Bs[kk][n] = v;
        }
        __syncthreads();

        #pragma unroll
        for (int q = 0; q < BKC; q++) {
            float4 a0 = *(const float4*)&As[q][tx * 4];
            float4 a1 = *(const float4*)&As[q][64 + tx * 4];
            // B pairs come straight out of smem as packed f32x2
            ulonglong2 bb0 = *(const ulonglong2*)&Bs[q][ty * 4];
            ulonglong2 bb1 = *(const ulonglong2*)&Bs[q][64 + ty * 4];
            u64 bn2[4] = {bb0.x, bb0.y, bb1.x, bb1.y};
            float am[8] = {a0.x, a0.y, a0.z, a0.w, a1.x, a1.y, a1.z, a1.w};
            #pragma unroll
            for (int i = 0; i < 8; i++) {
                u64 am2 = pack2(am[i], am[i]);
                #pragma unroll
                for (int j = 0; j < 4; j++)
                    fma2(acc[i][j], am2, bn2[j]);
            }
        }
        __syncthreads();
    }

    // Epilogue: unpack pairs, add bias, float4 stores.
    #pragma unroll
    for (int ih = 0; ih < 2; ih++) {
        #pragma unroll
        for (int i = 0; i < 4; i++) {
            int row = mBase + ih * 64 + tx * 4 + i;
            #pragma unroll
            for (int jh = 0; jh < 2; jh++) {
                int col = nBase + jh * 64 + ty * 4;
                if (col < Nn) {
                    float4 bv = *(const float4*)&bias[col];
                    float x0, x1, x2, x3;
                    unpack2(x0, x1, acc[ih * 4 + i][jh * 2 + 0]);
                    unpack2(x2, x3, acc[ih * 4 + i][jh * 2 + 1]);
                    float4 r;
                    r.x = x0 + bv.x;
                    r.y = x1 + bv.y;
                    r.z = x2 + bv.z;
                    r.w = x3 + bv.w;
                    *(float4*)&Cout[(size_t)row * Nn + col] = r;
                }
            }
        }
    }
}

// ---------------------------------------------------------------------------
// Window attention. Grid (BATCH, NHEADS, 2). 128 threads, 4 warps.
//   z = 0: source = Ys  -> typeA = attn_cv (scale),  typeB = attn_sh (scale^2)
//   z = 1: source = Ye  -> typeA = attn_sv (1.0),    typeB = attn_ch (scale)
// Lane owns one query row; FFMA2 everywhere:
//   QK: elementwise-pair dot product (q pairs x k pairs, horizontal add)
//   PV: output-dim pairs, p duplicated once per j
// ---------------------------------------------------------------------------
#define TP 36                                  // tile pitch (floats)
#define TSZ (NTOK * TP)                        // 2304 floats per tile
#define SP 65                                  // score/bias pitch
#define ATTN_SMEM ((4 * TSZ + 2 * NTOK * SP) * sizeof(float))   // 70144 B

__global__ __launch_bounds__(128)
void attn_kernel(const float* __restrict__ tcv, const float* __restrict__ tsv,
                 const float* __restrict__ tch, const float* __restrict__ tsh,
                 const int*   __restrict__ rel_idx)
{
    extern __shared__ float sm[];
    float* tiles = sm;                 // [4][64][TP]
    float* biasS = sm + 4 * TSZ;       // [2][64][SP] : bias, then scores

    const int b = blockIdx.x;
    const int h = blockIdx.y;
    const int z = blockIdx.z;

    const float* Y    = z ? g_Ye : g_Ys;
    const float* tblA = z ? tsv : tcv;
    const float* tblB = z ? tch : tsh;
    const float  sclA = z ? 1.0f  : SCALE;
    const float  sclB = z ? SCALE : SCALE * SCALE;
    float* outAp = z ? g_Msv : g_Mcv;
    float* outBp = z ? g_Mch : g_Msh;

    const int t    = threadIdx.x;
    const int lane = t & 31;
    const int warp = t >> 5;

    // ---- load 4 projection tiles [64][32] (cols j4*96 + h*32 + lane) ----
    #pragma unroll
    for (int j4 = 0; j4 < 4; j4++) {
        #pragma unroll
        for (int r = 0; r < 16; r++) {
            int i = warp * 16 + r;
            tiles[j4 * TSZ + i * TP + lane] =
                Y[(size_t)(b * NTOK + i) * K4 + j4 * CDIM + h * HD + lane];
        }
    }

    // ---- gather relative-position bias into score buffer ----
    for (int idx = t; idx < NTOK * NTOK; idx += 128) {
        int r = rel_idx[idx];
        int i = idx >> 6, j = idx & 63;
        biasS[i * SP + j]                  = tblA[r * NHEADS + h];
        biasS[NTOK * SP + i * SP + j]      = tblB[r * NHEADS + h];
    }
    __syncthreads();

    const int   type = warp >> 1;     // 0 = A, 1 = B
    const int   half = warp & 1;      // query-row half
    const int   row  = half * 32 + lane;
    const float scl  = type ? sclB : sclA;
    const float* Kt  = tiles;                 // j4 = 0 (keys)
    const float* Vt  = tiles + TSZ;           // j4 = 1 (values)
    const float* qp  = tiles + (2 + type) * TSZ + row * TP;
    float* St        = biasS + type * NTOK * SP + row * SP;   // my score row
    float* outP      = type ? outBp : outAp;

    // ---- q row into registers as 16 packed pairs ----
    u64 qr2[16];
    #pragma unroll
    for (int c = 0; c < 8; c++) {
        ulonglong2 v2 = *(const ulonglong2*)(qp + 4 * c);
        qr2[2 * c + 0] = v2.x;
        qr2[2 * c + 1] = v2.y;
    }

    // ---- scores: S[row][j] = scl * <q_row, k_j> + bias (pairwise dot) ----
    #pragma unroll 4
    for (int j = 0; j < NTOK; j++) {
        const float* kj = Kt + j * TP;
        u64 sA = 0ull, sB = 0ull, sC = 0ull, sD = 0ull;
        #pragma unroll
        for (int c = 0; c < 4; c++) {
            ulonglong2 k0 = *(const ulonglong2*)(kj + 8 * c);       // broadcast
            ulonglong2 k1 = *(const ulonglong2*)(kj + 8 * c + 4);
            fma2(sA, qr2[4 * c + 0], k0.x);
            fma2(sB, qr2[4 * c + 1], k0.y);
            fma2(sC, qr2[4 * c + 2], k1.x);
            fma2(sD, qr2[4 * c + 3], k1.y);
        }
        float a0, a1, b0, b1, c0, c1, d0, d1;
        unpack2(a0, a1, sA); unpack2(b0, b1, sB);
        unpack2(c0, c1, sC); unpack2(d0, d1, sD);
        float s = ((a0 + a1) + (b0 + b1)) + ((c0 + c1) + (d0 + d1));
        St[j] = fmaf(scl, s, St[j]);
    }

    // ---- softmax over my row (FMA-pipe exp; normalization deferred) ----
    float mx = -1e30f;
    #pragma unroll
    for (int j = 0; j < NTOK; j++) mx = fmaxf(mx, St[j]);
    float sum = 0.f;
    #pragma unroll
    for (int j = 0; j < NTOK; j++) {
        float e = fast_exp(St[j] - mx);
        St[j] = e;
        sum += e;
    }
    const float inv = 1.f / sum;

    // ---- out pairs: ou2[c] += p2 * v_pair, c = 16 pairs (32 dims) ----
    u64 ou2[16];
    #pragma unroll
    for (int c = 0; c < 16; c++) ou2[c] = 0ull;
    #pragma unroll 4
    for (int j = 0; j < NTOK; j++) {
        const float p = St[j];
        const u64 p2 = pack2(p, p);
        const float* vj = Vt + j * TP;
        #pragma unroll
        for (int c = 0; c < 8; c++) {
            ulonglong2 vv = *(const ulonglong2*)(vj + 4 * c);   // broadcast
            fma2(ou2[2 * c + 0], p2, vv.x);
            fma2(ou2[2 * c + 1], p2, vv.y);
        }
    }
    float* op = outP + (size_t)(b * NTOK + row) * CDIM + h * HD;
    #pragma unroll
    for (int c = 0; c < 8; c++) {
        float x0, x1, x2, x3;
        unpack2(x0, x1, ou2[2 * c + 0]);
        unpack2(x2, x3, ou2[2 * c + 1]);
        float4 r;
        r.x = x0 * inv; r.y = x1 * inv; r.z = x2 * inv; r.w = x3 * inv;
        *(float4*)(op + 4 * c) = r;
    }
}

// ---------------------------------------------------------------------------
// Launch
// ---------------------------------------------------------------------------
extern "C" void kernel_launch(void* const* d_in, const int* in_sizes, int n_in,
                              void* d_out, int out_size)
{
    const float* input_x = (const float*)d_in[0];
    const float* state_x = (const float*)d_in[1];
    const float* Ws      = (const float*)d_in[2];
    const float* bs      = (const float*)d_in[3];
    const float* We      = (const float*)d_in[4];
    const float* be      = (const float*)d_in[5];
    const float* tcv     = (const float*)d_in[6];
    const float* tsv     = (const float*)d_in[7];
    const float* tch     = (const float*)d_in[8];
    const float* tsh     = (const float*)d_in[9];
    const float* Wpv     = (const float*)d_in[10];
    const float* bpv     = (const float*)d_in[11];
    const float* Wph     = (const float*)d_in[12];
    const float* bph     = (const float*)d_in[13];
    const int*   rel_idx = (const int*)d_in[14];

    float* out   = (float*)d_out;
    float* state = out + (size_t)BATCH * NTOK * CDIM;

    float *pYs, *pYe, *pMcv, *pMsv, *pMch, *pMsh;
    cudaGetSymbolAddress((void**)&pYs,  g_Ys);
    cudaGetSymbolAddress((void**)&pYe,  g_Ye);
    cudaGetSymbolAddress((void**)&pMcv, g_Mcv);
    cudaGetSymbolAddress((void**)&pMsv, g_Msv);
    cudaGetSymbolAddress((void**)&pMch, g_Mch);
    cudaGetSymbolAddress((void**)&pMsh, g_Msh);

    cudaFuncSetAttribute(attn_kernel,
                         cudaFuncAttributeMaxDynamicSharedMemorySize,
                         (int)ATTN_SMEM);

    const int M = BATCH * NTOK;          // 262144

    // Stage 1: projections  Y = X @ W^T + b   -> [M, 384]
    {
        dim3 grid(M / BM, K4 / BN);      // (2048, 3)
        gemm_bias<<<grid, 256>>>(state_x, state_x, CDIM, CDIM, CDIM, CDIM, K4,
                                 Ws, bs, pYs);
        gemm_bias<<<grid, 256>>>(input_x, input_x, CDIM, CDIM, CDIM, CDIM, K4,
                                 We, be, pYe);
    }

    // Stage 2: 4 window attentions per (b, h)
    {
        dim3 grid(BATCH, NHEADS, 2);
        attn_kernel<<<grid, 128, ATTN_SMEM>>>(tcv, tsv, tch, tsh, rel_idx);
    }

    // Stage 3: output projections on concatenated merges
    {
        dim3 grid(M / BM, (CDIM + BN - 1) / BN);   // (2048, 1)
        gemm_bias<<<grid, 256>>>(pMcv, pMsv, CDIM, CDIM, CDIM, 2 * CDIM, CDIM,
                                 Wpv, bpv, out);
        gemm_bias<<<grid, 256>>>(pMch, pMsh, CDIM, CDIM, CDIM, 2 * CDIM, CDIM,
                                 Wph, bph, state);
    }
}